// round 13
// baseline (speedup 1.0000x reference)
#include <cuda_runtime.h>
#include <cuda_fp16.h>
#include <math.h>
#include <stdint.h>

// Problem constants
#define Bq    8
#define Tt    512
#define BT    4096      // B*T
#define Dd    1024
#define Hh    16
#define KVHh  4
#define HDd   64
#define Ll    4
#define Vv    32000
#define FFd   4096
#define QKVD  1536      // H*HD + 2*KVH*HD

typedef __half f16;

// ---------------------------------------------------------------------------
// Scratch (static device globals; no allocations allowed)
// ---------------------------------------------------------------------------
__device__ float g_x[BT * Dd];        // residual stream (fp32)
__device__ float g_qkv[BT * QKVD];    // qkv projection (rope in place, fp32)

__device__ f16 g_h[BT * Dd];          // layernorm output (fp16)
__device__ f16 g_y[BT * Dd];          // attention output (fp16)
__device__ f16 g_mlp[BT * FFd];       // gelu(fc) output (fp16)

// Transposed + split weights ([N][K] layout, fp16 hi/lo)
__device__ f16 g_wqkv_hi[Ll * QKVD * Dd];
__device__ f16 g_wqkv_lo[Ll * QKVD * Dd];
__device__ f16 g_wap_hi [Ll * Dd * Dd];     // single-pass (no lo)
__device__ f16 g_wfc_hi [Ll * FFd * Dd];
__device__ f16 g_wfc_lo [Ll * FFd * Dd];
__device__ f16 g_wmp_hi [Ll * Dd * FFd];    // single-pass (no lo)
__device__ f16 g_wlm_hi [Vv * Dd];          // single-pass (no lo)

// ---------------------------------------------------------------------------
// Weight transpose + split:  W[K][N] fp32  ->  out[N][K] fp16 hi(/lo)
// ---------------------------------------------------------------------------
__global__ void wconv_kernel(const float* __restrict__ W,
                             f16* __restrict__ oh, f16* __restrict__ ol,
                             int K, int N) {
    __shared__ float tile[32][33];
    int z = blockIdx.z;
    const float* Wz = W + (size_t)z * K * N;
    size_t ob = (size_t)z * K * N;
    int kb = blockIdx.y * 32, nb = blockIdx.x * 32;
    int tx = threadIdx.x, ty = threadIdx.y;
#pragma unroll
    for (int i = 0; i < 4; i++)
        tile[ty + 8 * i][tx] = Wz[(size_t)(kb + ty + 8 * i) * N + nb + tx];
    __syncthreads();
#pragma unroll
    for (int i = 0; i < 4; i++) {
        float v = tile[tx][ty + 8 * i];
        f16 h = __float2half_rn(v);
        size_t o = ob + (size_t)(nb + ty + 8 * i) * K + kb + tx;
        oh[o] = h;
        if (ol) ol[o] = __float2half_rn(v - __half2float(h));
    }
}

// ---------------------------------------------------------------------------
// Embedding gather
// ---------------------------------------------------------------------------
__global__ void embed_kernel(const int* __restrict__ ids,
                             const float* __restrict__ wte,
                             float* __restrict__ x) {
    int row = blockIdx.x;
    int tok = ids[row];
    const float4* src = (const float4*)(wte + (size_t)tok * Dd);
    float4* dst = (float4*)(x + (size_t)row * Dd);
    for (int i = threadIdx.x; i < Dd / 4; i += blockDim.x) dst[i] = src[i];
}

// ---------------------------------------------------------------------------
// LayerNorm -> fp16
// ---------------------------------------------------------------------------
__global__ void ln_kernel(const float* __restrict__ x,
                          const float* __restrict__ gamma,
                          const float* __restrict__ beta,
                          f16* __restrict__ oh) {
    int row = blockIdx.x;
    const float* xr = x + (size_t)row * Dd;
    int t = threadIdx.x;
    float v[4];
    float s = 0.f, sq = 0.f;
#pragma unroll
    for (int i = 0; i < 4; i++) {
        float val = xr[t + i * 256];
        v[i] = val; s += val; sq += val * val;
    }
#pragma unroll
    for (int o = 16; o > 0; o >>= 1) {
        s  += __shfl_xor_sync(0xFFFFFFFFu, s, o);
        sq += __shfl_xor_sync(0xFFFFFFFFu, sq, o);
    }
    __shared__ float ss[8], sqq[8];
    int wid = t >> 5, lane = t & 31;
    if (lane == 0) { ss[wid] = s; sqq[wid] = sq; }
    __syncthreads();
    if (t == 0) {
        float a = 0.f, b = 0.f;
#pragma unroll
        for (int i = 0; i < 8; i++) { a += ss[i]; b += sqq[i]; }
        ss[0] = a; sqq[0] = b;
    }
    __syncthreads();
    float mean = ss[0] * (1.0f / Dd);
    float var  = sqq[0] * (1.0f / Dd) - mean * mean;
    float inv  = rsqrtf(var + 1e-5f);
#pragma unroll
    for (int i = 0; i < 4; i++) {
        int c = t + i * 256;
        float o = (v[i] - mean) * inv * gamma[c] + beta[c];
        oh[(size_t)row * Dd + c] = __float2half_rn(o);
    }
}

// ---------------------------------------------------------------------------
// RoPE in place on qkv (fp32)
// ---------------------------------------------------------------------------
__global__ void rope_kernel(float* __restrict__ qkv) {
    int row = blockIdx.x;
    int t = row % Tt;
    float* qr = qkv + (size_t)row * QKVD;
    const float ft = (float)t;
    for (int idx = threadIdx.x; idx < (Hh + KVHh) * (HDd / 2); idx += blockDim.x) {
        int head = idx >> 5;
        int i    = idx & 31;
        int base = (head < Hh) ? head * HDd : Dd + (head - Hh) * HDd;
        float inv = expf(-((2.0f * i) / (float)HDd) * 9.210340371976184f);
        float ang = ft * inv;
        float c, s;
        sincosf(ang, &s, &c);
        float u0 = qr[base + 2 * i];
        float u1 = qr[base + 2 * i + 1];
        qr[base + 2 * i]     = u0 * c - u1 * s;
        qr[base + 2 * i + 1] = u0 * s + u1 * c;
    }
}

// ---------------------------------------------------------------------------
// Causal flash attention: 256 threads = 64 q-rows x 4 GQA heads sharing one
// KV head's tiles. Tile-max softmax (one rescale per 64-key tile).
// grid: (T/64, KVH, B).
// ---------------------------------------------------------------------------
#define ATTN_SMEM ((4096 + 4096 + 4 * 64 * 65) * 4)

__global__ void __launch_bounds__(256) attn_kernel(const float* __restrict__ qkv,
                                                   f16* __restrict__ y) {
    extern __shared__ float asm_[];
    float* Ks = asm_;                 // [64][64]
    float* Vs = asm_ + 4096;          // [64][64]
    float* S  = asm_ + 8192;          // [4][64][65]

    int qt = blockIdx.x, kvh = blockIdx.y, b = blockIdx.z;
    int tid = threadIdx.x;
    int qr = tid & 63;                // query row within tile
    int hsub = tid >> 6;              // 0..3
    int h = kvh * 4 + hsub;           // q head (h/4 == kvh)
    int qglob = qt * 64 + qr;
    int qrow = b * Tt + qglob;
    const float* qp = qkv + (size_t)qrow * QKVD + h * HDd;

    float q[HDd];
#pragma unroll
    for (int d = 0; d < HDd; d++) q[d] = qp[d];
    float acc[HDd];
#pragma unroll
    for (int d = 0; d < HDd; d++) acc[d] = 0.f;
    float m = -1e30f, l = 0.f;

    float* Srow = S + (hsub * 64 + qr) * 65;

    const float* Kbase = qkv + (size_t)(b * Tt) * QKVD + Dd + kvh * HDd;
    const float* Vbase = Kbase + KVHh * HDd;
    const float scale = 0.125f;

    for (int kt = 0; kt <= qt; kt++) {
        const float* Kb = Kbase + (size_t)kt * 64 * QKVD;
        const float* Vb = Vbase + (size_t)kt * 64 * QKVD;
        __syncthreads();
        for (int id = tid; id < 2048; id += 256) {
            int r = (id & 1023) >> 4, dg = id & 15;
            float* dst = (id < 1024) ? Ks : Vs;
            const float* src = (id < 1024) ? Kb : Vb;
            ((float4*)(dst + r * 64))[dg] = *(const float4*)(src + (size_t)r * QKVD + dg * 4);
        }
        __syncthreads();
        int jmax = (kt == qt) ? (qr + 1) : 64;
        float tmax = -1e30f;
        for (int j = 0; j < jmax; j++) {
            float s = 0.f;
            const float* kr = Ks + j * 64;
#pragma unroll
            for (int d = 0; d < HDd; d++) s += q[d] * kr[d];
            s *= scale;
            Srow[j] = s;
            tmax = fmaxf(tmax, s);
        }
        if (tmax > m) {
            float corr = __expf(m - tmax);
            l *= corr;
#pragma unroll
            for (int d = 0; d < HDd; d++) acc[d] *= corr;
            m = tmax;
        }
        for (int j = 0; j < jmax; j++) {
            float p = __expf(Srow[j] - m);
            l += p;
            const float* vr = Vs + j * 64;
#pragma unroll
            for (int d = 0; d < HDd; d++) acc[d] += p * vr[d];
        }
    }
    float invl = 1.f / l;
    size_t yo = (size_t)qrow * Dd + h * HDd;
#pragma unroll
    for (int d = 0; d < HDd; d++)
        y[yo + d] = __float2half_rn(acc[d] * invl);
}

// ---------------------------------------------------------------------------
// GEMM (fp16, PASSES-compensated): C[M,N] = A[M,K] @ W[N,K]^T (+bias, epilogue)
//   A fp16 single; W split hi(+lo when PASSES==2). fp32 accumulate.
// Grid: (BT/128, N/256), 256 threads, __launch_bounds__(256,2) -> 2 CTAs/SM.
// mma.sync (R6 config): two 128-col halves, BK=32, 2-stage double buffer,
// warp tile 64x32, LDS.32 fragment loads. SMEM = 61,440 B (2 stages x 30 KB).
// EPI 0: bias + fp32 out.  EPI 1: bias + GELU + fp16 out.  EPI 2: bias+res+fp32.
// ---------------------------------------------------------------------------
#define TM 128
#define TN 256
#define FB_SMEM 61440   // 2 stages * 15360 halves * 2B

__device__ __forceinline__ void cpasync16p(void* dst, const void* src) {
    uint32_t d = (uint32_t)__cvta_generic_to_shared(dst);
    asm volatile("cp.async.cg.shared.global [%0], [%1], 16;\n" :: "r"(d), "l"(src));
}

#define MMAF16(d, a, b)                                                       \
    asm volatile(                                                             \
        "mma.sync.aligned.m16n8k16.row.col.f32.f16.f16.f32 "                  \
        "{%0,%1,%2,%3}, {%4,%5,%6,%7}, {%8,%9}, {%0,%1,%2,%3};"               \
        : "+f"((d)[0]), "+f"((d)[1]), "+f"((d)[2]), "+f"((d)[3])              \
        : "r"((a)[0]), "r"((a)[1]), "r"((a)[2]), "r"((a)[3]),                 \
          "r"((b)[0]), "r"((b)[1]))

template <int EPI, int PASSES>
__global__ void __launch_bounds__(256, 2) gemm_any(
    const f16* __restrict__ A, const f16* __restrict__ Wh, const f16* __restrict__ Wl,
    const float* __restrict__ bias, const float* __restrict__ res,
    float* __restrict__ C, f16* __restrict__ Cout, int N, int K) {
    extern __shared__ __align__(1024) char sm[];
    const int tid = threadIdx.x;
    const int wid = tid >> 5, lane = tid & 31;
    const int rowBase = blockIdx.x * TM;
    const int colBase = blockIdx.y * TN;

    const int warpM = wid >> 2, warpN = wid & 3;   // 2 x 4 warps, tile 64x32
    f16* smh = (f16*)sm;
    const int LDA = 40;           // 32 + 8 pad (halves)
    const int SCH = 128 * 40;     // halves per array (5120)
    const int SST = 3 * SCH;      // halves per stage (15360)
    const int niter = K >> 5;
    const int NPRE = (PASSES == 2) ? 6 : 4;   // 16B chunks: 1536 or 1024

    for (int hf = 0; hf < 2; ++hf) {
        const int cb = colBase + hf * 128;
        float acc[4][4][4];
#pragma unroll
        for (int a = 0; a < 4; a++)
#pragma unroll
            for (int b = 0; b < 4; b++)
#pragma unroll
                for (int c = 0; c < 4; c++) acc[a][b][c] = 0.f;

#define FB_PREFETCH(stage, kt)                                                \
        {                                                                     \
            f16* sb = smh + (stage) * SST;                                    \
            _Pragma("unroll")                                                 \
            for (int u = 0; u < NPRE; ++u) {                                  \
                int id = tid + u * 256;                                       \
                int arr = id >> 9;                                            \
                int q = id & 511;                                             \
                int r = q >> 2, seg = q & 3;                                  \
                const f16* src = (arr == 0) ? A : ((arr == 1) ? Wh : Wl);     \
                int rg = ((arr == 0) ? rowBase : cb) + r;                     \
                cpasync16p(sb + arr * SCH + r * LDA + seg * 8,                \
                           src + (size_t)rg * K + (kt) + seg * 8);            \
            }                                                                 \
            asm volatile("cp.async.commit_group;");                           \
        }

        FB_PREFETCH(0, 0);

        for (int it = 0; it < niter; ++it) {
            if (it + 1 < niter) {
                FB_PREFETCH((it + 1) & 1, (it + 1) << 5);
                asm volatile("cp.async.wait_group 1;");
            } else {
                asm volatile("cp.async.wait_group 0;");
            }
            __syncthreads();

            const f16* sA  = smh + (it & 1) * SST;
            const f16* sBh = sA + SCH;
            const f16* sBl = sA + 2 * SCH;

#pragma unroll
            for (int k0 = 0; k0 < 32; k0 += 16) {
                uint32_t ah[4][4], bh[4][2], bl[4][2];
                const int col = k0 + (lane & 3) * 2;
#pragma unroll
                for (int mt = 0; mt < 4; ++mt) {
                    int r = warpM * 64 + mt * 16 + (lane >> 2);
                    const f16* p = sA + r * LDA + col;
                    ah[mt][0] = *(const uint32_t*)p;
                    ah[mt][1] = *(const uint32_t*)(p + 8 * LDA);
                    ah[mt][2] = *(const uint32_t*)(p + 8);
                    ah[mt][3] = *(const uint32_t*)(p + 8 * LDA + 8);
                }
#pragma unroll
                for (int nt = 0; nt < 4; ++nt) {
                    int n = warpN * 32 + nt * 8 + (lane >> 2);
                    const f16* p = sBh + n * LDA + col;
                    bh[nt][0] = *(const uint32_t*)p;
                    bh[nt][1] = *(const uint32_t*)(p + 8);
                    if (PASSES == 2) {
                        const f16* q = sBl + n * LDA + col;
                        bl[nt][0] = *(const uint32_t*)q;
                        bl[nt][1] = *(const uint32_t*)(q + 8);
                    }
                }
#pragma unroll
                for (int mt = 0; mt < 4; ++mt)
#pragma unroll
                    for (int nt = 0; nt < 4; ++nt) {
                        MMAF16(acc[mt][nt], ah[mt], bh[nt]);
                        if (PASSES == 2) MMAF16(acc[mt][nt], ah[mt], bl[nt]);
                    }
            }
            __syncthreads();
        }
#undef FB_PREFETCH

        // Epilogue for this half
#pragma unroll
        for (int mt = 0; mt < 4; ++mt) {
#pragma unroll
            for (int nt = 0; nt < 4; ++nt) {
                int r0 = rowBase + warpM * 64 + mt * 16 + (lane >> 2);
                int c0 = cb + warpN * 32 + nt * 8 + (lane & 3) * 2;
                float v0 = acc[mt][nt][0], v1 = acc[mt][nt][1];
                float v2 = acc[mt][nt][2], v3 = acc[mt][nt][3];
                if (bias) {
                    float b0 = bias[c0], b1 = bias[c0 + 1];
                    v0 += b0; v1 += b1; v2 += b0; v3 += b1;
                }
                if (EPI == 1) {
                    v0 = 0.5f * v0 * (1.f + erff(v0 * 0.70710678118654752f));
                    v1 = 0.5f * v1 * (1.f + erff(v1 * 0.70710678118654752f));
                    v2 = 0.5f * v2 * (1.f + erff(v2 * 0.70710678118654752f));
                    v3 = 0.5f * v3 * (1.f + erff(v3 * 0.70710678118654752f));
                    __half2 p0, p1;
                    p0.x = __float2half_rn(v0); p0.y = __float2half_rn(v1);
                    p1.x = __float2half_rn(v2); p1.y = __float2half_rn(v3);
                    *(__half2*)(Cout + (size_t)r0 * N + c0) = p0;
                    *(__half2*)(Cout + (size_t)(r0 + 8) * N + c0) = p1;
                } else {
                    if (EPI == 2) {
                        float2 ra = *(const float2*)(res + (size_t)r0 * N + c0);
                        float2 rb = *(const float2*)(res + (size_t)(r0 + 8) * N + c0);
                        v0 += ra.x; v1 += ra.y; v2 += rb.x; v3 += rb.y;
                    }
                    float2 o0; o0.x = v0; o0.y = v1;
                    float2 o1; o1.x = v2; o1.y = v3;
                    *(float2*)(C + (size_t)r0 * N + c0) = o0;
                    *(float2*)(C + (size_t)(r0 + 8) * N + c0) = o1;
                }
            }
        }
        __syncthreads();
    }
}

// ---------------------------------------------------------------------------
// Launch
// ---------------------------------------------------------------------------
extern "C" void kernel_launch(void* const* d_in, const int* in_sizes, int n_in,
                              void* d_out, int out_size) {
    const int*   ids      = (const int*)d_in[0];
    const float* wte      = (const float*)d_in[1];
    const float* ln1_g    = (const float*)d_in[2];
    const float* ln1_b    = (const float*)d_in[3];
    const float* c_attn_w = (const float*)d_in[4];
    const float* c_attn_b = (const float*)d_in[5];
    const float* c_proj_w = (const float*)d_in[6];
    const float* c_proj_b = (const float*)d_in[7];
    const float* ln2_g    = (const float*)d_in[8];
    const float* ln2_b    = (const float*)d_in[9];
    const float* fc_w     = (const float*)d_in[10];
    const float* fc_b     = (const float*)d_in[11];
    const float* proj_w   = (const float*)d_in[12];
    const float* proj_b   = (const float*)d_in[13];
    const float* lnf_g    = (const float*)d_in[14];
    const float* lnf_b    = (const float*)d_in[15];
    const float* lm_w     = (const float*)d_in[16];
    float* out = (float*)d_out;

    float *x, *qkv;
    f16 *h, *y, *mlp;
    f16 *wqkv_hi, *wqkv_lo, *wap_hi, *wfc_hi, *wfc_lo, *wmp_hi, *wlm_hi;
    cudaGetSymbolAddress((void**)&x,    g_x);
    cudaGetSymbolAddress((void**)&qkv,  g_qkv);
    cudaGetSymbolAddress((void**)&h,    g_h);
    cudaGetSymbolAddress((void**)&y,    g_y);
    cudaGetSymbolAddress((void**)&mlp,  g_mlp);
    cudaGetSymbolAddress((void**)&wqkv_hi, g_wqkv_hi);
    cudaGetSymbolAddress((void**)&wqkv_lo, g_wqkv_lo);
    cudaGetSymbolAddress((void**)&wap_hi,  g_wap_hi);
    cudaGetSymbolAddress((void**)&wfc_hi,  g_wfc_hi);
    cudaGetSymbolAddress((void**)&wfc_lo,  g_wfc_lo);
    cudaGetSymbolAddress((void**)&wmp_hi,  g_wmp_hi);
    cudaGetSymbolAddress((void**)&wlm_hi,  g_wlm_hi);

    cudaFuncSetAttribute(gemm_any<0, 2>, cudaFuncAttributeMaxDynamicSharedMemorySize, FB_SMEM);
    cudaFuncSetAttribute(gemm_any<0, 1>, cudaFuncAttributeMaxDynamicSharedMemorySize, FB_SMEM);
    cudaFuncSetAttribute(gemm_any<1, 2>, cudaFuncAttributeMaxDynamicSharedMemorySize, FB_SMEM);
    cudaFuncSetAttribute(gemm_any<2, 1>, cudaFuncAttributeMaxDynamicSharedMemorySize, FB_SMEM);
    cudaFuncSetAttribute(attn_kernel, cudaFuncAttributeMaxDynamicSharedMemorySize, ATTN_SMEM);

    dim3 t32x8(32, 8);

    // Weight conversion (transpose + split; proj & LM head hi-only)
    wconv_kernel<<<dim3(QKVD / 32, Dd / 32, Ll), t32x8>>>(c_attn_w, wqkv_hi, wqkv_lo, Dd, QKVD);
    wconv_kernel<<<dim3(Dd / 32, Dd / 32, Ll),   t32x8>>>(c_proj_w, wap_hi,  nullptr, Dd, Dd);
    wconv_kernel<<<dim3(FFd / 32, Dd / 32, Ll),  t32x8>>>(fc_w,     wfc_hi,  wfc_lo,  Dd, FFd);
    wconv_kernel<<<dim3(Dd / 32, FFd / 32, Ll),  t32x8>>>(proj_w,   wmp_hi,  nullptr, FFd, Dd);
    wconv_kernel<<<dim3(Vv / 32, Dd / 32, 1),    t32x8>>>(lm_w,     wlm_hi,  nullptr, Dd, Vv);

    embed_kernel<<<BT, 256>>>(ids, wte, x);

    for (int l = 0; l < Ll; l++) {
        // LN1 -> h (fp16)
        ln_kernel<<<BT, 256>>>(x, ln1_g + (size_t)l * Dd, ln1_b + (size_t)l * Dd, h);
        // QKV projection (2-pass, fp32 out)
        gemm_any<0, 2><<<dim3(BT / TM, QKVD / TN), 256, FB_SMEM>>>(
            h, wqkv_hi + (size_t)l * QKVD * Dd, wqkv_lo + (size_t)l * QKVD * Dd,
            c_attn_b + (size_t)l * QKVD, nullptr, qkv, nullptr, QKVD, Dd);
        // RoPE
        rope_kernel<<<BT, 256>>>(qkv);
        // Attention -> y (fp16)
        attn_kernel<<<dim3(Tt / 64, KVHh, Bq), 256, ATTN_SMEM>>>(qkv, y);
        // Attn out projection + residual (single-pass, fp32 into x)
        gemm_any<2, 1><<<dim3(BT / TM, Dd / TN), 256, FB_SMEM>>>(
            y, wap_hi + (size_t)l * Dd * Dd, nullptr,
            c_proj_b + (size_t)l * Dd, x, x, nullptr, Dd, Dd);
        // LN2 -> h (fp16)
        ln_kernel<<<BT, 256>>>(x, ln2_g + (size_t)l * Dd, ln2_b + (size_t)l * Dd, h);
        // FC + GELU -> mlp (2-pass, fp16 out)
        gemm_any<1, 2><<<dim3(BT / TM, FFd / TN), 256, FB_SMEM>>>(
            h, wfc_hi + (size_t)l * FFd * Dd, wfc_lo + (size_t)l * FFd * Dd,
            fc_b + (size_t)l * FFd, nullptr, nullptr, mlp, FFd, Dd);
        // MLP projection + residual (single-pass, fp32 into x)
        gemm_any<2, 1><<<dim3(BT / TM, Dd / TN), 256, FB_SMEM>>>(
            mlp, wmp_hi + (size_t)l * Dd * FFd, nullptr,
            proj_b + (size_t)l * Dd, x, x, nullptr, Dd, FFd);
    }

    // Final LN + LM head (single-pass fp16 weights)
    ln_kernel<<<BT, 256>>>(x, lnf_g, lnf_b, h);
    gemm_any<0, 1><<<dim3(BT / TM, Vv / TN), 256, FB_SMEM>>>(
        h, wlm_hi, nullptr, nullptr, nullptr, out, nullptr, Vv, Dd);
}

// round 17
// speedup vs baseline: 1.0744x; 1.0744x over previous
#include <cuda_runtime.h>
#include <cuda_fp16.h>
#include <math.h>
#include <stdint.h>

// Problem constants
#define Bq    8
#define Tt    512
#define BT    4096      // B*T
#define Dd    1024
#define Hh    16
#define KVHh  4
#define HDd   64
#define Ll    4
#define Vv    32000
#define FFd   4096
#define QKVD  1536      // H*HD + 2*KVH*HD

typedef __half f16;

// ---------------------------------------------------------------------------
// Scratch (static device globals; no allocations allowed)
// ---------------------------------------------------------------------------
__device__ float g_x[BT * Dd];        // residual stream (fp32)
__device__ float g_qkv[BT * QKVD];    // qkv projection (rope in place, fp32)

__device__ f16 g_h[BT * Dd];          // layernorm output (fp16)
__device__ f16 g_y[BT * Dd];          // attention output (fp16)
__device__ f16 g_mlp[BT * FFd];       // gelu(fc) output (fp16)

// Transposed + split weights ([N][K] layout, fp16 hi/lo)
__device__ f16 g_wqkv_hi[Ll * QKVD * Dd];
__device__ f16 g_wqkv_lo[Ll * QKVD * Dd];
__device__ f16 g_wap_hi [Ll * Dd * Dd];     // single-pass (no lo)
__device__ f16 g_wfc_hi [Ll * FFd * Dd];    // single-pass (no lo)
__device__ f16 g_wmp_hi [Ll * Dd * FFd];    // single-pass (no lo)
__device__ f16 g_wlm_hi [Vv * Dd];          // single-pass (no lo)

// ---------------------------------------------------------------------------
// Weight transpose + split:  W[K][N] fp32  ->  out[N][K] fp16 hi(/lo)
// ---------------------------------------------------------------------------
__global__ void wconv_kernel(const float* __restrict__ W,
                             f16* __restrict__ oh, f16* __restrict__ ol,
                             int K, int N) {
    __shared__ float tile[32][33];
    int z = blockIdx.z;
    const float* Wz = W + (size_t)z * K * N;
    size_t ob = (size_t)z * K * N;
    int kb = blockIdx.y * 32, nb = blockIdx.x * 32;
    int tx = threadIdx.x, ty = threadIdx.y;
#pragma unroll
    for (int i = 0; i < 4; i++)
        tile[ty + 8 * i][tx] = Wz[(size_t)(kb + ty + 8 * i) * N + nb + tx];
    __syncthreads();
#pragma unroll
    for (int i = 0; i < 4; i++) {
        float v = tile[tx][ty + 8 * i];
        f16 h = __float2half_rn(v);
        size_t o = ob + (size_t)(nb + ty + 8 * i) * K + kb + tx;
        oh[o] = h;
        if (ol) ol[o] = __float2half_rn(v - __half2float(h));
    }
}

// ---------------------------------------------------------------------------
// Embedding gather
// ---------------------------------------------------------------------------
__global__ void embed_kernel(const int* __restrict__ ids,
                             const float* __restrict__ wte,
                             float* __restrict__ x) {
    int row = blockIdx.x;
    int tok = ids[row];
    const float4* src = (const float4*)(wte + (size_t)tok * Dd);
    float4* dst = (float4*)(x + (size_t)row * Dd);
    for (int i = threadIdx.x; i < Dd / 4; i += blockDim.x) dst[i] = src[i];
}

// ---------------------------------------------------------------------------
// LayerNorm -> fp16
// ---------------------------------------------------------------------------
__global__ void ln_kernel(const float* __restrict__ x,
                          const float* __restrict__ gamma,
                          const float* __restrict__ beta,
                          f16* __restrict__ oh) {
    int row = blockIdx.x;
    const float* xr = x + (size_t)row * Dd;
    int t = threadIdx.x;
    float v[4];
    float s = 0.f, sq = 0.f;
#pragma unroll
    for (int i = 0; i < 4; i++) {
        float val = xr[t + i * 256];
        v[i] = val; s += val; sq += val * val;
    }
#pragma unroll
    for (int o = 16; o > 0; o >>= 1) {
        s  += __shfl_xor_sync(0xFFFFFFFFu, s, o);
        sq += __shfl_xor_sync(0xFFFFFFFFu, sq, o);
    }
    __shared__ float ss[8], sqq[8];
    int wid = t >> 5, lane = t & 31;
    if (lane == 0) { ss[wid] = s; sqq[wid] = sq; }
    __syncthreads();
    if (t == 0) {
        float a = 0.f, b = 0.f;
#pragma unroll
        for (int i = 0; i < 8; i++) { a += ss[i]; b += sqq[i]; }
        ss[0] = a; sqq[0] = b;
    }
    __syncthreads();
    float mean = ss[0] * (1.0f / Dd);
    float var  = sqq[0] * (1.0f / Dd) - mean * mean;
    float inv  = rsqrtf(var + 1e-5f);
#pragma unroll
    for (int i = 0; i < 4; i++) {
        int c = t + i * 256;
        float o = (v[i] - mean) * inv * gamma[c] + beta[c];
        oh[(size_t)row * Dd + c] = __float2half_rn(o);
    }
}

// ---------------------------------------------------------------------------
// RoPE in place on qkv (fp32)
// ---------------------------------------------------------------------------
__global__ void rope_kernel(float* __restrict__ qkv) {
    int row = blockIdx.x;
    int t = row % Tt;
    float* qr = qkv + (size_t)row * QKVD;
    const float ft = (float)t;
    for (int idx = threadIdx.x; idx < (Hh + KVHh) * (HDd / 2); idx += blockDim.x) {
        int head = idx >> 5;
        int i    = idx & 31;
        int base = (head < Hh) ? head * HDd : Dd + (head - Hh) * HDd;
        float inv = expf(-((2.0f * i) / (float)HDd) * 9.210340371976184f);
        float ang = ft * inv;
        float c, s;
        sincosf(ang, &s, &c);
        float u0 = qr[base + 2 * i];
        float u1 = qr[base + 2 * i + 1];
        qr[base + 2 * i]     = u0 * c - u1 * s;
        qr[base + 2 * i + 1] = u0 * s + u1 * c;
    }
}

// ---------------------------------------------------------------------------
// Causal flash attention: 256 threads = 64 q-rows x 4 GQA heads sharing one
// KV head's tiles. Tile-max softmax (one rescale per 64-key tile).
// grid: (T/64, KVH, B).
// ---------------------------------------------------------------------------
#define ATTN_SMEM ((4096 + 4096 + 4 * 64 * 65) * 4)

__global__ void __launch_bounds__(256) attn_kernel(const float* __restrict__ qkv,
                                                   f16* __restrict__ y) {
    extern __shared__ float asm_[];
    float* Ks = asm_;                 // [64][64]
    float* Vs = asm_ + 4096;          // [64][64]
    float* S  = asm_ + 8192;          // [4][64][65]

    int qt = blockIdx.x, kvh = blockIdx.y, b = blockIdx.z;
    int tid = threadIdx.x;
    int qr = tid & 63;                // query row within tile
    int hsub = tid >> 6;              // 0..3
    int h = kvh * 4 + hsub;           // q head (h/4 == kvh)
    int qglob = qt * 64 + qr;
    int qrow = b * Tt + qglob;
    const float* qp = qkv + (size_t)qrow * QKVD + h * HDd;

    float q[HDd];
#pragma unroll
    for (int d = 0; d < HDd; d++) q[d] = qp[d];
    float acc[HDd];
#pragma unroll
    for (int d = 0; d < HDd; d++) acc[d] = 0.f;
    float m = -1e30f, l = 0.f;

    float* Srow = S + (hsub * 64 + qr) * 65;

    const float* Kbase = qkv + (size_t)(b * Tt) * QKVD + Dd + kvh * HDd;
    const float* Vbase = Kbase + KVHh * HDd;
    const float scale = 0.125f;

    for (int kt = 0; kt <= qt; kt++) {
        const float* Kb = Kbase + (size_t)kt * 64 * QKVD;
        const float* Vb = Vbase + (size_t)kt * 64 * QKVD;
        __syncthreads();
        for (int id = tid; id < 2048; id += 256) {
            int r = (id & 1023) >> 4, dg = id & 15;
            float* dst = (id < 1024) ? Ks : Vs;
            const float* src = (id < 1024) ? Kb : Vb;
            ((float4*)(dst + r * 64))[dg] = *(const float4*)(src + (size_t)r * QKVD + dg * 4);
        }
        __syncthreads();
        int jmax = (kt == qt) ? (qr + 1) : 64;
        float tmax = -1e30f;
        for (int j = 0; j < jmax; j++) {
            float s = 0.f;
            const float* kr = Ks + j * 64;
#pragma unroll
            for (int d = 0; d < HDd; d++) s += q[d] * kr[d];
            s *= scale;
            Srow[j] = s;
            tmax = fmaxf(tmax, s);
        }
        if (tmax > m) {
            float corr = __expf(m - tmax);
            l *= corr;
#pragma unroll
            for (int d = 0; d < HDd; d++) acc[d] *= corr;
            m = tmax;
        }
        for (int j = 0; j < jmax; j++) {
            float p = __expf(Srow[j] - m);
            l += p;
            const float* vr = Vs + j * 64;
#pragma unroll
            for (int d = 0; d < HDd; d++) acc[d] += p * vr[d];
        }
    }
    float invl = 1.f / l;
    size_t yo = (size_t)qrow * Dd + h * HDd;
#pragma unroll
    for (int d = 0; d < HDd; d++)
        y[yo + d] = __float2half_rn(acc[d] * invl);
}

// ---------------------------------------------------------------------------
// GEMM (fp16, PASSES-compensated): C[M,N] = A[M,K] @ W[N,K]^T (+bias, epilogue)
//   A fp16 single; W split hi(+lo when PASSES==2). fp32 accumulate.
// Grid: (BT/128, N/256), 256 threads (natural regs; 1 CTA/SM — R13 showed the
// 2-CTA reg cap spills). mma.sync R6 config: two 128-col halves, BK=32,
// 2-stage double buffer, warp tile 64x32, LDS.32 fragment loads.
// EPI 0: bias + fp32 out.  EPI 1: bias + GELU + fp16 out.  EPI 2: bias+res+fp32.
// ---------------------------------------------------------------------------
#define TM 128
#define TN 256
#define FB_SMEM 61440   // 2 stages * 15360 halves * 2B

__device__ __forceinline__ void cpasync16p(void* dst, const void* src) {
    uint32_t d = (uint32_t)__cvta_generic_to_shared(dst);
    asm volatile("cp.async.cg.shared.global [%0], [%1], 16;\n" :: "r"(d), "l"(src));
}

#define MMAF16(d, a, b)                                                       \
    asm volatile(                                                             \
        "mma.sync.aligned.m16n8k16.row.col.f32.f16.f16.f32 "                  \
        "{%0,%1,%2,%3}, {%4,%5,%6,%7}, {%8,%9}, {%0,%1,%2,%3};"               \
        : "+f"((d)[0]), "+f"((d)[1]), "+f"((d)[2]), "+f"((d)[3])              \
        : "r"((a)[0]), "r"((a)[1]), "r"((a)[2]), "r"((a)[3]),                 \
          "r"((b)[0]), "r"((b)[1]))

template <int EPI, int PASSES>
__global__ void __launch_bounds__(256) gemm_any(
    const f16* __restrict__ A, const f16* __restrict__ Wh, const f16* __restrict__ Wl,
    const float* __restrict__ bias, const float* __restrict__ res,
    float* __restrict__ C, f16* __restrict__ Cout, int N, int K) {
    extern __shared__ __align__(1024) char sm[];
    const int tid = threadIdx.x;
    const int wid = tid >> 5, lane = tid & 31;
    const int rowBase = blockIdx.x * TM;
    const int colBase = blockIdx.y * TN;

    const int warpM = wid >> 2, warpN = wid & 3;   // 2 x 4 warps, tile 64x32
    f16* smh = (f16*)sm;
    const int LDA = 40;           // 32 + 8 pad (halves)
    const int SCH = 128 * 40;     // halves per array (5120)
    const int SST = 3 * SCH;      // halves per stage (15360)
    const int niter = K >> 5;
    const int NPRE = (PASSES == 2) ? 6 : 4;   // 16B chunks: 1536 or 1024

    for (int hf = 0; hf < 2; ++hf) {
        const int cb = colBase + hf * 128;
        float acc[4][4][4];
#pragma unroll
        for (int a = 0; a < 4; a++)
#pragma unroll
            for (int b = 0; b < 4; b++)
#pragma unroll
                for (int c = 0; c < 4; c++) acc[a][b][c] = 0.f;

#define FB_PREFETCH(stage, kt)                                                \
        {                                                                     \
            f16* sb = smh + (stage) * SST;                                    \
            _Pragma("unroll")                                                 \
            for (int u = 0; u < NPRE; ++u) {                                  \
                int id = tid + u * 256;                                       \
                int arr = id >> 9;                                            \
                int q = id & 511;                                             \
                int r = q >> 2, seg = q & 3;                                  \
                const f16* src = (arr == 0) ? A : ((arr == 1) ? Wh : Wl);     \
                int rg = ((arr == 0) ? rowBase : cb) + r;                     \
                cpasync16p(sb + arr * SCH + r * LDA + seg * 8,                \
                           src + (size_t)rg * K + (kt) + seg * 8);            \
            }                                                                 \
            asm volatile("cp.async.commit_group;");                           \
        }

        FB_PREFETCH(0, 0);

        for (int it = 0; it < niter; ++it) {
            if (it + 1 < niter) {
                FB_PREFETCH((it + 1) & 1, (it + 1) << 5);
                asm volatile("cp.async.wait_group 1;");
            } else {
                asm volatile("cp.async.wait_group 0;");
            }
            __syncthreads();

            const f16* sA  = smh + (it & 1) * SST;
            const f16* sBh = sA + SCH;
            const f16* sBl = sA + 2 * SCH;

#pragma unroll
            for (int k0 = 0; k0 < 32; k0 += 16) {
                uint32_t ah[4][4], bh[4][2], bl[4][2];
                const int col = k0 + (lane & 3) * 2;
#pragma unroll
                for (int mt = 0; mt < 4; ++mt) {
                    int r = warpM * 64 + mt * 16 + (lane >> 2);
                    const f16* p = sA + r * LDA + col;
                    ah[mt][0] = *(const uint32_t*)p;
                    ah[mt][1] = *(const uint32_t*)(p + 8 * LDA);
                    ah[mt][2] = *(const uint32_t*)(p + 8);
                    ah[mt][3] = *(const uint32_t*)(p + 8 * LDA + 8);
                }
#pragma unroll
                for (int nt = 0; nt < 4; ++nt) {
                    int n = warpN * 32 + nt * 8 + (lane >> 2);
                    const f16* p = sBh + n * LDA + col;
                    bh[nt][0] = *(const uint32_t*)p;
                    bh[nt][1] = *(const uint32_t*)(p + 8);
                    if (PASSES == 2) {
                        const f16* q = sBl + n * LDA + col;
                        bl[nt][0] = *(const uint32_t*)q;
                        bl[nt][1] = *(const uint32_t*)(q + 8);
                    }
                }
#pragma unroll
                for (int mt = 0; mt < 4; ++mt)
#pragma unroll
                    for (int nt = 0; nt < 4; ++nt) {
                        MMAF16(acc[mt][nt], ah[mt], bh[nt]);
                        if (PASSES == 2) MMAF16(acc[mt][nt], ah[mt], bl[nt]);
                    }
            }
            __syncthreads();
        }
#undef FB_PREFETCH

        // Epilogue for this half
#pragma unroll
        for (int mt = 0; mt < 4; ++mt) {
#pragma unroll
            for (int nt = 0; nt < 4; ++nt) {
                int r0 = rowBase + warpM * 64 + mt * 16 + (lane >> 2);
                int c0 = cb + warpN * 32 + nt * 8 + (lane & 3) * 2;
                float v0 = acc[mt][nt][0], v1 = acc[mt][nt][1];
                float v2 = acc[mt][nt][2], v3 = acc[mt][nt][3];
                if (bias) {
                    float b0 = bias[c0], b1 = bias[c0 + 1];
                    v0 += b0; v1 += b1; v2 += b0; v3 += b1;
                }
                if (EPI == 1) {
                    v0 = 0.5f * v0 * (1.f + erff(v0 * 0.70710678118654752f));
                    v1 = 0.5f * v1 * (1.f + erff(v1 * 0.70710678118654752f));
                    v2 = 0.5f * v2 * (1.f + erff(v2 * 0.70710678118654752f));
                    v3 = 0.5f * v3 * (1.f + erff(v3 * 0.70710678118654752f));
                    __half2 p0, p1;
                    p0.x = __float2half_rn(v0); p0.y = __float2half_rn(v1);
                    p1.x = __float2half_rn(v2); p1.y = __float2half_rn(v3);
                    *(__half2*)(Cout + (size_t)r0 * N + c0) = p0;
                    *(__half2*)(Cout + (size_t)(r0 + 8) * N + c0) = p1;
                } else {
                    if (EPI == 2) {
                        float2 ra = *(const float2*)(res + (size_t)r0 * N + c0);
                        float2 rb = *(const float2*)(res + (size_t)(r0 + 8) * N + c0);
                        v0 += ra.x; v1 += ra.y; v2 += rb.x; v3 += rb.y;
                    }
                    float2 o0; o0.x = v0; o0.y = v1;
                    float2 o1; o1.x = v2; o1.y = v3;
                    *(float2*)(C + (size_t)r0 * N + c0) = o0;
                    *(float2*)(C + (size_t)(r0 + 8) * N + c0) = o1;
                }
            }
        }
        __syncthreads();
    }
}

// ---------------------------------------------------------------------------
// Launch
// ---------------------------------------------------------------------------
extern "C" void kernel_launch(void* const* d_in, const int* in_sizes, int n_in,
                              void* d_out, int out_size) {
    const int*   ids      = (const int*)d_in[0];
    const float* wte      = (const float*)d_in[1];
    const float* ln1_g    = (const float*)d_in[2];
    const float* ln1_b    = (const float*)d_in[3];
    const float* c_attn_w = (const float*)d_in[4];
    const float* c_attn_b = (const float*)d_in[5];
    const float* c_proj_w = (const float*)d_in[6];
    const float* c_proj_b = (const float*)d_in[7];
    const float* ln2_g    = (const float*)d_in[8];
    const float* ln2_b    = (const float*)d_in[9];
    const float* fc_w     = (const float*)d_in[10];
    const float* fc_b     = (const float*)d_in[11];
    const float* proj_w   = (const float*)d_in[12];
    const float* proj_b   = (const float*)d_in[13];
    const float* lnf_g    = (const float*)d_in[14];
    const float* lnf_b    = (const float*)d_in[15];
    const float* lm_w     = (const float*)d_in[16];
    float* out = (float*)d_out;

    float *x, *qkv;
    f16 *h, *y, *mlp;
    f16 *wqkv_hi, *wqkv_lo, *wap_hi, *wfc_hi, *wmp_hi, *wlm_hi;
    cudaGetSymbolAddress((void**)&x,    g_x);
    cudaGetSymbolAddress((void**)&qkv,  g_qkv);
    cudaGetSymbolAddress((void**)&h,    g_h);
    cudaGetSymbolAddress((void**)&y,    g_y);
    cudaGetSymbolAddress((void**)&mlp,  g_mlp);
    cudaGetSymbolAddress((void**)&wqkv_hi, g_wqkv_hi);
    cudaGetSymbolAddress((void**)&wqkv_lo, g_wqkv_lo);
    cudaGetSymbolAddress((void**)&wap_hi,  g_wap_hi);
    cudaGetSymbolAddress((void**)&wfc_hi,  g_wfc_hi);
    cudaGetSymbolAddress((void**)&wmp_hi,  g_wmp_hi);
    cudaGetSymbolAddress((void**)&wlm_hi,  g_wlm_hi);

    cudaFuncSetAttribute(gemm_any<0, 2>, cudaFuncAttributeMaxDynamicSharedMemorySize, FB_SMEM);
    cudaFuncSetAttribute(gemm_any<0, 1>, cudaFuncAttributeMaxDynamicSharedMemorySize, FB_SMEM);
    cudaFuncSetAttribute(gemm_any<1, 1>, cudaFuncAttributeMaxDynamicSharedMemorySize, FB_SMEM);
    cudaFuncSetAttribute(gemm_any<2, 1>, cudaFuncAttributeMaxDynamicSharedMemorySize, FB_SMEM);
    cudaFuncSetAttribute(attn_kernel, cudaFuncAttributeMaxDynamicSharedMemorySize, ATTN_SMEM);

    dim3 t32x8(32, 8);

    // Weight conversion (transpose + split; only QKV keeps lo)
    wconv_kernel<<<dim3(QKVD / 32, Dd / 32, Ll), t32x8>>>(c_attn_w, wqkv_hi, wqkv_lo, Dd, QKVD);
    wconv_kernel<<<dim3(Dd / 32, Dd / 32, Ll),   t32x8>>>(c_proj_w, wap_hi,  nullptr, Dd, Dd);
    wconv_kernel<<<dim3(FFd / 32, Dd / 32, Ll),  t32x8>>>(fc_w,     wfc_hi,  nullptr, Dd, FFd);
    wconv_kernel<<<dim3(Dd / 32, FFd / 32, Ll),  t32x8>>>(proj_w,   wmp_hi,  nullptr, FFd, Dd);
    wconv_kernel<<<dim3(Vv / 32, Dd / 32, 1),    t32x8>>>(lm_w,     wlm_hi,  nullptr, Dd, Vv);

    embed_kernel<<<BT, 256>>>(ids, wte, x);

    for (int l = 0; l < Ll; l++) {
        // LN1 -> h (fp16)
        ln_kernel<<<BT, 256>>>(x, ln1_g + (size_t)l * Dd, ln1_b + (size_t)l * Dd, h);
        // QKV projection (2-pass, fp32 out)
        gemm_any<0, 2><<<dim3(BT / TM, QKVD / TN), 256, FB_SMEM>>>(
            h, wqkv_hi + (size_t)l * QKVD * Dd, wqkv_lo + (size_t)l * QKVD * Dd,
            c_attn_b + (size_t)l * QKVD, nullptr, qkv, nullptr, QKVD, Dd);
        // RoPE
        rope_kernel<<<BT, 256>>>(qkv);
        // Attention -> y (fp16)
        attn_kernel<<<dim3(Tt / 64, KVHh, Bq), 256, ATTN_SMEM>>>(qkv, y);
        // Attn out projection + residual (single-pass, fp32 into x)
        gemm_any<2, 1><<<dim3(BT / TM, Dd / TN), 256, FB_SMEM>>>(
            y, wap_hi + (size_t)l * Dd * Dd, nullptr,
            c_proj_b + (size_t)l * Dd, x, x, nullptr, Dd, Dd);
        // LN2 -> h (fp16)
        ln_kernel<<<BT, 256>>>(x, ln2_g + (size_t)l * Dd, ln2_b + (size_t)l * Dd, h);
        // FC + GELU -> mlp (single-pass, fp16 out)
        gemm_any<1, 1><<<dim3(BT / TM, FFd / TN), 256, FB_SMEM>>>(
            h, wfc_hi + (size_t)l * FFd * Dd, nullptr,
            fc_b + (size_t)l * FFd, nullptr, nullptr, mlp, FFd, Dd);
        // MLP projection + residual (single-pass, fp32 into x)
        gemm_any<2, 1><<<dim3(BT / TM, Dd / TN), 256, FB_SMEM>>>(
            mlp, wmp_hi + (size_t)l * Dd * FFd, nullptr,
            proj_b + (size_t)l * Dd, x, x, nullptr, Dd, FFd);
    }

    // Final LN + LM head (single-pass fp16 weights)
    ln_kernel<<<BT, 256>>>(x, lnf_g, lnf_b, h);
    gemm_any<0, 1><<<dim3(BT / TM, Vv / TN), 256, FB_SMEM>>>(
        h, wlm_hi, nullptr, nullptr, nullptr, out, nullptr, Vv, Dd);
}